// round 3
// baseline (speedup 1.0000x reference)
#include <cuda_runtime.h>
#include <cuda_bf16.h>
#include <cstdint>

#define N_NODES 50000
#define N_EDGES 800000
#define IN_CH   128
#define H_CH    128
#define NCAT    256   // W_l and W_r stacked

// ---------------- device scratch (no allocations allowed) ----------------
__device__ float d_w[NCAT * IN_CH];            // packed [W_l; W_r], row-major [256,128]
__device__ float d_g[N_NODES * NCAT];          // row n: [g_l(128) | g_r(128)]
__device__ int   d_count[N_NODES];             // histogram of in-degree
__device__ int   d_start[N_NODES + 1];         // CSR offsets by dst
__device__ int   d_cursor[N_NODES];            // scatter cursors
__device__ int   d_src_sorted[N_EDGES];        // src node per sorted edge
__device__ float d_env_sorted[N_EDGES];        // envelope per sorted edge

// ---------------- kernel 1: pack W ----------------
__global__ void pack_w_kernel(const float* __restrict__ Wl, const float* __restrict__ Wr) {
    int i = blockIdx.x * blockDim.x + threadIdx.x;
    if (i < H_CH * IN_CH) {
        d_w[i] = Wl[i];
        d_w[H_CH * IN_CH + i] = Wr[i];
    }
}

// ---------------- kernel 2: SGEMM  C[M,256] = q[M,128] @ Wcat^T ----------------
// BM=64, BN=64, BK=16, 256 threads, 4x4 register tile
#define BM 64
#define BN 64
#define BK 16
#define PAD 68   // padded row length for smem tiles

__global__ __launch_bounds__(256) void gemm_kernel(const float* __restrict__ q) {
    __shared__ float As[BK][PAD];  // As[k][m]
    __shared__ float Bs[BK][PAD];  // Bs[k][n]

    const int block_m = blockIdx.x * BM;
    const int block_n = blockIdx.y * BN;
    const int tid = threadIdx.x;
    const int tn = tid & 15;       // 0..15
    const int tm = tid >> 4;       // 0..15

    // load indices: 256 threads load 64x16 tile as float4
    const int lrow  = tid >> 2;          // 0..63
    const int lcol4 = (tid & 3) << 2;    // 0,4,8,12

    float acc[4][4];
#pragma unroll
    for (int i = 0; i < 4; i++)
#pragma unroll
        for (int j = 0; j < 4; j++) acc[i][j] = 0.f;

#pragma unroll
    for (int k0 = 0; k0 < IN_CH; k0 += BK) {
        // A tile: q[block_m+lrow][k0+lcol4 .. +3]
        float4 av = make_float4(0.f, 0.f, 0.f, 0.f);
        int arow = block_m + lrow;
        if (arow < N_NODES)
            av = *reinterpret_cast<const float4*>(&q[arow * IN_CH + k0 + lcol4]);
        As[lcol4 + 0][lrow] = av.x;
        As[lcol4 + 1][lrow] = av.y;
        As[lcol4 + 2][lrow] = av.z;
        As[lcol4 + 3][lrow] = av.w;
        // B tile: Wcat[block_n+lrow][k0+lcol4 .. +3]  (block_n+lrow < 256 always)
        float4 bv = *reinterpret_cast<const float4*>(&d_w[(block_n + lrow) * IN_CH + k0 + lcol4]);
        Bs[lcol4 + 0][lrow] = bv.x;
        Bs[lcol4 + 1][lrow] = bv.y;
        Bs[lcol4 + 2][lrow] = bv.z;
        Bs[lcol4 + 3][lrow] = bv.w;
        __syncthreads();

#pragma unroll
        for (int kk = 0; kk < BK; kk++) {
            float4 a = *reinterpret_cast<const float4*>(&As[kk][tm << 2]);
            float4 b = *reinterpret_cast<const float4*>(&Bs[kk][tn << 2]);
            float ar[4] = {a.x, a.y, a.z, a.w};
            float br[4] = {b.x, b.y, b.z, b.w};
#pragma unroll
            for (int i = 0; i < 4; i++)
#pragma unroll
                for (int j = 0; j < 4; j++) acc[i][j] += ar[i] * br[j];
        }
        __syncthreads();
    }

#pragma unroll
    for (int i = 0; i < 4; i++) {
        int row = block_m + (tm << 2) + i;
        if (row < N_NODES) {
            float4 o = make_float4(acc[i][0], acc[i][1], acc[i][2], acc[i][3]);
            *reinterpret_cast<float4*>(&d_g[row * NCAT + block_n + (tn << 2)]) = o;
        }
    }
}

// ---------------- kernel 3: zero counts ----------------
__global__ void zero_counts_kernel() {
    int i = blockIdx.x * blockDim.x + threadIdx.x;
    if (i < N_NODES) d_count[i] = 0;
}

// ---------------- kernel 4: histogram of dst ----------------
__global__ void hist_kernel(const int* __restrict__ ei) {
    int i = blockIdx.x * blockDim.x + threadIdx.x;
    if (i < N_EDGES) {
        int dst = ei[N_EDGES + i];
        atomicAdd(&d_count[dst], 1);
    }
}

// ---------------- kernel 5: exclusive scan (single block) ----------------
__global__ __launch_bounds__(1024) void scan_kernel() {
    __shared__ int wt[32];
    __shared__ int carry_s;
    int tid = threadIdx.x;
    if (tid == 0) carry_s = 0;
    __syncthreads();

    for (int base = 0; base < N_NODES; base += 1024) {
        int idx = base + tid;
        int v = (idx < N_NODES) ? d_count[idx] : 0;
        // warp inclusive scan
        int x = v;
#pragma unroll
        for (int off = 1; off < 32; off <<= 1) {
            int y = __shfl_up_sync(0xffffffffu, x, off);
            if ((tid & 31) >= off) x += y;
        }
        if ((tid & 31) == 31) wt[tid >> 5] = x;
        __syncthreads();
        if (tid < 32) {
            int y = wt[tid];
#pragma unroll
            for (int off = 1; off < 32; off <<= 1) {
                int z = __shfl_up_sync(0xffffffffu, y, off);
                if (tid >= off) y += z;
            }
            wt[tid] = y;
        }
        __syncthreads();
        int incl = x + ((tid >= 32) ? wt[(tid >> 5) - 1] : 0);
        int carry = carry_s;
        int excl = carry + incl - v;
        if (idx < N_NODES) { d_start[idx] = excl; d_cursor[idx] = excl; }
        __syncthreads();
        if (tid == 1023) carry_s = carry + incl;  // chunk total (tail padded with 0)
        __syncthreads();
    }
    if (tid == 0) d_start[N_NODES] = carry_s;
}

// ---------------- kernel 6: scatter edges into dst-sorted order ----------------
__global__ void scatter_kernel(const int* __restrict__ ei,
                               const float* __restrict__ envelope) {
    int i = blockIdx.x * blockDim.x + threadIdx.x;
    if (i < N_EDGES) {
        int src = ei[i];
        int dst = ei[N_EDGES + i];
        int pos = atomicAdd(&d_cursor[dst], 1);
        d_src_sorted[pos] = src;
        d_env_sorted[pos] = envelope[i];
    }
}

// ---------------- kernel 7: per-node softmax + aggregation (warp per node) ----------------
__global__ __launch_bounds__(256) void out_kernel(const float* __restrict__ attn_w,
                                                  float* __restrict__ out) {
    int warp_id = (blockIdx.x * blockDim.x + threadIdx.x) >> 5;
    if (warp_id >= N_NODES) return;
    int lane = threadIdx.x & 31;
    int n = warp_id;

    // per-lane 4-channel slice of g_r[n] and attn_w
    float4 gr = *reinterpret_cast<const float4*>(&d_g[n * NCAT + H_CH + (lane << 2)]);
    float4 aw = *reinterpret_cast<const float4*>(&attn_w[lane << 2]);

    float acc0 = 0.f, acc1 = 0.f, acc2 = 0.f, acc3 = 0.f;
    float denom = 0.f;

    int js = d_start[n];
    int je = d_start[n + 1];

    for (int j = js; j < je; j++) {
        int src = d_src_sorted[j];
        float env = d_env_sorted[j];
        float4 gl = *reinterpret_cast<const float4*>(&d_g[src * NCAT + (lane << 2)]);

        float t0 = gl.x + gr.x;
        float t1 = gl.y + gr.y;
        float t2 = gl.z + gr.z;
        float t3 = gl.w + gr.w;
        // silu(t) = t / (1 + e^-t)
        float s0 = t0 * __frcp_rn(1.f + __expf(-t0));
        float s1 = t1 * __frcp_rn(1.f + __expf(-t1));
        float s2 = t2 * __frcp_rn(1.f + __expf(-t2));
        float s3 = t3 * __frcp_rn(1.f + __expf(-t3));
        float p = s0 * aw.x + s1 * aw.y + s2 * aw.z + s3 * aw.w;
        // warp reduce (all lanes get full sum)
#pragma unroll
        for (int off = 16; off > 0; off >>= 1)
            p += __shfl_xor_sync(0xffffffffu, p, off);

        float ex = __expf(p) * (env + 1e-7f);
        denom += ex;
        acc0 += ex * gl.x;
        acc1 += ex * gl.y;
        acc2 += ex * gl.z;
        acc3 += ex * gl.w;
    }

    float inv = (denom > 0.f) ? (1.f / denom) : 0.f;
    float4 o = make_float4(acc0 * inv, acc1 * inv, acc2 * inv, acc3 * inv);
    *reinterpret_cast<float4*>(&out[n * H_CH + (lane << 2)]) = o;
}

// ---------------- launch ----------------
extern "C" void kernel_launch(void* const* d_in, const int* in_sizes, int n_in,
                              void* d_out, int out_size) {
    const float* q        = (const float*)d_in[0];
    // d_in[1] = k (unused), d_in[2] = v (unused)
    const float* envelope = (const float*)d_in[3];
    const float* W_l      = (const float*)d_in[4];
    const float* W_r      = (const float*)d_in[5];
    const float* attn_w   = (const float*)d_in[6];
    const int*   ei       = (const int*)d_in[7];   // JAX x64-disabled: int32
    float* out = (float*)d_out;

    // 1. pack weights
    pack_w_kernel<<<(H_CH * IN_CH + 255) / 256, 256>>>(W_l, W_r);

    // 2. fused GEMM: g = q @ [W_l;W_r]^T
    dim3 ggrid((N_NODES + BM - 1) / BM, NCAT / BN);
    gemm_kernel<<<ggrid, 256>>>(q);

    // 3-6. counting sort of edges by dst
    zero_counts_kernel<<<(N_NODES + 255) / 256, 256>>>();
    hist_kernel<<<(N_EDGES + 255) / 256, 256>>>(ei);
    scan_kernel<<<1, 1024>>>();
    scatter_kernel<<<(N_EDGES + 255) / 256, 256>>>(ei, envelope);

    // 7. warp-per-node softmax aggregation
    int total_threads = N_NODES * 32;
    out_kernel<<<(total_threads + 255) / 256, 256>>>(attn_w, out);
}